// round 8
// baseline (speedup 1.0000x reference)
#include <cuda_runtime.h>
#include <cuda_fp16.h>

// Problem constants (fixed by the reference: m = n = 8192, 50 Sinkhorn iters, beta=0.3)
#define MDIM  8192
#define NBLK  148          // <= SM count -> one resident wave at occ 1
#define TPB   512
#define NITER 50
#define BETA  0.3f

// ---- scratch (device globals: no allocation allowed in kernel_launch) ----
static __device__ __half g_E[(size_t)MDIM * MDIM];      // E = exp(s) in fp16 (128 MB)
static __device__ float  g_w[MDIM];                     // w_j = exp(v_j)
static __device__ float  g_z[MDIM];                     // z_i = exp(u_i) (last iteration's)
static __device__ float  g_part[(size_t)NBLK * MDIM];   // per-block column partial sums
static __device__ float  g_losspart[NBLK];              // per-block loss partials
static __device__ unsigned g_cnt;                       // grid-barrier arrive counter
static __device__ unsigned g_gen;                       // grid-barrier generation

__device__ __forceinline__ float warp_sum(float v) {
#pragma unroll
    for (int o = 16; o; o >>= 1) v += __shfl_xor_sync(0xffffffffu, v, o);
    return v;
}
__device__ __forceinline__ float warp_max(float v) {
#pragma unroll
    for (int o = 16; o; o >>= 1) v = fmaxf(v, __shfl_xor_sync(0xffffffffu, v, o));
    return v;
}

// Device-wide barrier: all NBLK CTAs resident (one wave, occ 1). Deterministic.
__device__ __forceinline__ void grid_bar(unsigned want) {
    __syncthreads();
    if (threadIdx.x == 0) {
        __threadfence();
        unsigned a = atomicAdd(&g_cnt, 1u);
        if (a == NBLK - 1u) {
            atomicExch(&g_cnt, 0u);
            __threadfence();
            atomicExch(&g_gen, want);           // release
        } else {
            while (*((volatile unsigned*)&g_gen) < want) __nanosleep(64);
        }
        __threadfence();                         // acquire
    }
    __syncthreads();
}

// barrier reset + w <- 1  (runs once per graph replay)
__global__ void k_init() {
    int j = blockIdx.x * blockDim.x + threadIdx.x;
    if (j < MDIM) g_w[j] = 1.0f;
    if (j == 0) { g_cnt = 0u; g_gen = 0u; }
}

// E = exp(s) in fp16 (one pass; iterations read half the bytes and do NO exp)
__global__ void k_convert(const float* __restrict__ in) {
    const float L2E = 1.4426950408889634f;
    size_t i = (size_t)blockIdx.x * blockDim.x + threadIdx.x;   // float4 index
    float4 f = reinterpret_cast<const float4*>(in)[i];
    float e0 = exp2f(f.x * L2E), e1 = exp2f(f.y * L2E);
    float e2 = exp2f(f.z * L2E), e3 = exp2f(f.w * L2E);
    union { uint2 u; __half2 h[2]; } P;
    P.h[0] = __floats2half2_rn(e0, e1);
    P.h[1] = __floats2half2_rn(e2, e3);
    reinterpret_cast<uint2*>(g_E)[i] = P.u;
}

// Persistent multiplicative Sinkhorn: 50 iterations, all-FMA inner loop.
//   S_i = sum_j E_ij * w_j ;  z_i = mu/S_i ;  colsum_j = sum_i E_ij * z_i ;  w_j = nu/colsum_j
// Thread t owns 16 columns {g*4096 + 8t .. +7 : g=0..1}; col accumulators in registers.
// Depth-2 row prefetch (32KB in flight/SM).
__global__ void __launch_bounds__(TPB, 1) k_sinkhorn() {
    const int tid = threadIdx.x;
    const int b   = blockIdx.x;
    const int r0  = (b * MDIM) / NBLK;
    const int r1  = ((b + 1) * MDIM) / NBLK;
    const float MUc = 6.103515625e-5f;       // mu = nu = 1/16384

    // column-reduce ownership: block b owns columns [c0, c1);
    // 8 groups of 64 lanes each sum up to 19 of the 148 partial rows.
    const int c0 = r0, nc = r1 - r0;
    const int cl = tid & 63;
    const int cg = tid >> 6;

    __shared__ float sred[16];
    __shared__ float csum[8][64];

    float w[2][8];
#pragma unroll
    for (int g = 0; g < 2; g++)
#pragma unroll
        for (int k = 0; k < 8; k++) w[g][k] = 1.0f;     // v = 0 at iteration 1

    // depth-2 prefetch (every block has >= 55 rows)
    uint4 raw[2][2];
    {
        const uint4* rA = reinterpret_cast<const uint4*>(g_E + (size_t)r0 * MDIM);
        const uint4* rB = reinterpret_cast<const uint4*>(g_E + (size_t)(r0 + 1) * MDIM);
#pragma unroll
        for (int g = 0; g < 2; g++) { raw[0][g] = rA[(g << 9) + tid]; raw[1][g] = rB[(g << 9) + tid]; }
    }

    unsigned gen = 0;

    for (int it = 0; it < NITER; it++) {
        // ---- row phase ----
        float cacc[2][8];
#pragma unroll
        for (int g = 0; g < 2; g++)
#pragma unroll
            for (int k = 0; k < 8; k++) cacc[g][k] = 0.f;

        for (int r = r0; r < r1; r++) {
            const int p = (r - r0) & 1;
            uint4 cur[2];
#pragma unroll
            for (int g = 0; g < 2; g++) cur[g] = raw[p][g];
            if (r + 2 < r1) {
                const uint4* row = reinterpret_cast<const uint4*>(g_E + (size_t)(r + 2) * MDIM);
#pragma unroll
                for (int g = 0; g < 2; g++) raw[p][g] = row[(g << 9) + tid];
            }

            float e[2][8];
            float lsum = 0.f;
#pragma unroll
            for (int g = 0; g < 2; g++) {
                union { uint4 u; __half2 h[4]; } P; P.u = cur[g];
#pragma unroll
                for (int q = 0; q < 4; q++) {
                    float2 f = __half22float2(P.h[q]);
                    e[g][2 * q]     = f.x;
                    e[g][2 * q + 1] = f.y;
                    lsum = fmaf(f.x, w[g][2 * q],     lsum);
                    lsum = fmaf(f.y, w[g][2 * q + 1], lsum);
                }
            }

            float ws = warp_sum(lsum);
            __syncthreads();                       // guard smem reuse from previous row
            if ((tid & 31) == 0) sred[tid >> 5] = ws;
            __syncthreads();
            float S = 0.f;
#pragma unroll
            for (int q = 0; q < 16; q++) S += sred[q];   // fixed order -> deterministic

            float zr = __fdividef(MUc, S);               // z_i = exp(u_i)
            if (tid == 0) g_z[r] = zr;                   // only last iteration's survives

#pragma unroll
            for (int g = 0; g < 2; g++)
#pragma unroll
                for (int k = 0; k < 8; k++)
                    cacc[g][k] = fmaf(e[g][k], zr, cacc[g][k]);
        }

        // writeout column partials
        {
            float* outp = g_part + (size_t)b * MDIM;
#pragma unroll
            for (int g = 0; g < 2; g++) {
                int cb = (g << 12) + (tid << 3);
                float4 o0, o1;
                o0.x = cacc[g][0]; o0.y = cacc[g][1]; o0.z = cacc[g][2]; o0.w = cacc[g][3];
                o1.x = cacc[g][4]; o1.y = cacc[g][5]; o1.z = cacc[g][6]; o1.w = cacc[g][7];
                *reinterpret_cast<float4*>(outp + cb)     = o0;
                *reinterpret_cast<float4*>(outp + cb + 4) = o1;
            }
        }

        grid_bar(++gen);    // partials visible everywhere

        // ---- column reduce: w_j = nu / sum_b P[b][j] for my columns ----
        {
            float s = 0.f;
            if (cl < nc) {
                const float* p = g_part + (size_t)(cg * 19) * MDIM + (c0 + cl);
#pragma unroll
                for (int k = 0; k < 19; k++)
                    if (cg * 19 + k < NBLK) s += p[(size_t)k * MDIM];
            }
            csum[cg][cl] = s;
            __syncthreads();
            if (cg == 0 && cl < nc) {
                float t = 0.f;
#pragma unroll
                for (int q = 0; q < 8; q++) t += csum[q][cl];    // fixed order
                g_w[c0 + cl] = __fdividef(MUc, t);
            }
        }

        // prefetch next iteration's first two rows (independent of w)
        if (it + 1 < NITER) {
            const uint4* rA = reinterpret_cast<const uint4*>(g_E + (size_t)r0 * MDIM);
            const uint4* rB = reinterpret_cast<const uint4*>(g_E + (size_t)(r0 + 1) * MDIM);
#pragma unroll
            for (int g = 0; g < 2; g++) { raw[0][g] = rA[(g << 9) + tid]; raw[1][g] = rB[(g << 9) + tid]; }
        }

        grid_bar(++gen);    // w visible everywhere

        if (it + 1 < NITER) {
#pragma unroll
            for (int g = 0; g < 2; g++) {
                int cb = (g << 12) + (tid << 3);
                float4 a = *reinterpret_cast<const float4*>(g_w + cb);
                float4 c = *reinterpret_cast<const float4*>(g_w + cb + 4);
                w[g][0] = a.x; w[g][1] = a.y; w[g][2] = a.z; w[g][3] = a.w;
                w[g][4] = c.x; w[g][5] = c.y; w[g][6] = c.z; w[g][7] = c.w;
            }
        }
    }
}

// Final loss pass over the fp32 matrix (depth-1 row prefetch, 512 threads):
//  L_i = LSE_j(scale*s) (max-shifted; scale=100 demands fp32 input)
//  base = exp(s+v) = exp(s)*w_j,  rowq = exp(u+log(m+n)) = z_i*16384
//  per_row = beta*(L*SumQ - scale*Sum(s*Q)) + (1-beta)*(L - scale*s_ii)
__global__ void __launch_bounds__(TPB, 1) k_final(const float* __restrict__ Sm,
                                                  const float* __restrict__ scale_p) {
    const int tid = threadIdx.x;
    const int b   = blockIdx.x;
    const int r0  = (b * MDIM) / NBLK;
    const int r1  = ((b + 1) * MDIM) / NBLK;
    const float L2E   = 1.4426950408889634f;
    const float scale = *scale_p;
    const float sL2E  = scale * L2E;

    float w[2][8];
#pragma unroll
    for (int g = 0; g < 2; g++) {
        int cb = (g << 12) + (tid << 3);
        float4 a = *reinterpret_cast<const float4*>(g_w + cb);
        float4 c = *reinterpret_cast<const float4*>(g_w + cb + 4);
        w[g][0] = a.x; w[g][1] = a.y; w[g][2] = a.z; w[g][3] = a.w;
        w[g][4] = c.x; w[g][5] = c.y; w[g][6] = c.z; w[g][7] = c.w;
    }

    __shared__ float smax[2][16], sA[2][16], sB[2][16], sC[2][16];
    __shared__ float sdiag[2];
    float rowloss = 0.f;

    float4 nxt[4];
    {
        const float4* row = reinterpret_cast<const float4*>(Sm + (size_t)r0 * MDIM);
#pragma unroll
        for (int g = 0; g < 2; g++) {
            nxt[2 * g]     = row[(g << 10) + (tid << 1)];
            nxt[2 * g + 1] = row[(g << 10) + (tid << 1) + 1];
        }
    }

    for (int r = r0; r < r1; r++) {
        const int p = (r - r0) & 1;
        float val[2][8];
#pragma unroll
        for (int g = 0; g < 2; g++) {
            float4 a = nxt[2 * g], c = nxt[2 * g + 1];
            val[g][0] = a.x; val[g][1] = a.y; val[g][2] = a.z; val[g][3] = a.w;
            val[g][4] = c.x; val[g][5] = c.y; val[g][6] = c.z; val[g][7] = c.w;
        }
        if (r + 1 < r1) {
            const float4* row = reinterpret_cast<const float4*>(Sm + (size_t)(r + 1) * MDIM);
#pragma unroll
            for (int g = 0; g < 2; g++) {
                nxt[2 * g]     = row[(g << 10) + (tid << 1)];
                nxt[2 * g + 1] = row[(g << 10) + (tid << 1) + 1];
            }
        }

        float m = val[0][0];
#pragma unroll
        for (int g = 0; g < 2; g++)
#pragma unroll
            for (int k = 0; k < 8; k++) m = fmaxf(m, val[g][k]);
        m = warp_max(m);

        if (tid == ((r & 4095) >> 3)) sdiag[p] = val[r >> 12][r & 7];  // owner of col r
        if ((tid & 31) == 0) smax[p][tid >> 5] = m;
        __syncthreads();
        float M = smax[p][0];
#pragma unroll
        for (int q = 1; q < 16; q++) M = fmaxf(M, smax[p][q]);

        float negML = -M * sL2E;
        float aE = 0.f, aB = 0.f, aSB = 0.f;
#pragma unroll
        for (int g = 0; g < 2; g++)
#pragma unroll
            for (int k = 0; k < 8; k++) {
                float s = val[g][k];
                aE += exp2f(fmaf(s, sL2E, negML));        // exp(scale*(s-M))
                float base = exp2f(s * L2E) * w[g][k];    // exp(s+v)
                aB += base;
                aSB = fmaf(s, base, aSB);
            }
        aE = warp_sum(aE); aB = warp_sum(aB); aSB = warp_sum(aSB);
        if ((tid & 31) == 0) { int q = tid >> 5; sA[p][q] = aE; sB[p][q] = aB; sC[p][q] = aSB; }
        __syncthreads();

        if (tid == 0) {
            float SE = 0.f, SBv = 0.f, SSv = 0.f;
#pragma unroll
            for (int q = 0; q < 16; q++) { SE += sA[p][q]; SBv += sB[p][q]; SSv += sC[p][q]; }
            float L    = fmaf(scale, M, __logf(SE));
            float rowq = g_z[r] * 16384.0f;               // exp(u + log(m+n))
            rowloss += BETA * (L * (SBv * rowq) - scale * (SSv * rowq))
                     + (1.f - BETA) * (L - scale * sdiag[p]);
        }
    }
    if (tid == 0) g_losspart[b] = rowloss;
}

// final scalar: mean over rows (fixed-order reduction -> deterministic)
__global__ void k_loss(float* __restrict__ out) {
    int tid = threadIdx.x;
    float v = (tid < NBLK) ? g_losspart[tid] : 0.f;
    v = warp_sum(v);
    __shared__ float sred[8];
    if ((tid & 31) == 0) sred[tid >> 5] = v;
    __syncthreads();
    if (tid == 0) {
        float t = 0.f;
#pragma unroll
        for (int q = 0; q < 8; q++) t += sred[q];
        out[0] = t / (float)MDIM;
    }
}

extern "C" void kernel_launch(void* const* d_in, const int* in_sizes, int n_in,
                              void* d_out, int out_size) {
    (void)in_sizes; (void)n_in; (void)out_size;
    const float* Sm    = (const float*)d_in[0];   // similarity_matrix [8192,8192] f32
    const float* scale = (const float*)d_in[1];   // logit_scale scalar f32
    float* out = (float*)d_out;

    k_init<<<MDIM / TPB, TPB>>>();
    k_convert<<<(int)(((size_t)MDIM * MDIM / 4) / TPB), TPB>>>(Sm);
    k_sinkhorn<<<NBLK, TPB>>>();
    k_final<<<NBLK, TPB>>>(Sm, scale);
    k_loss<<<1, TPB>>>(out);
}

// round 9
// speedup vs baseline: 1.7140x; 1.7140x over previous
#include <cuda_runtime.h>
#include <cuda_fp16.h>

// Problem constants (fixed by the reference: m = n = 8192, 50 Sinkhorn iters, beta=0.3)
#define MDIM  8192
#define NBLK  148          // <= SM count -> one resident wave at occ 1
#define TPB   512
#define NITER 50
#define BETA  0.3f

// ---- scratch (device globals: no allocation allowed in kernel_launch) ----
static __device__ __half g_E[(size_t)MDIM * MDIM];      // E = exp(s) in fp16 (128 MB)
static __device__ float  g_w[MDIM];                     // w_j = exp(v_j)
static __device__ float  g_z[MDIM];                     // z_i = exp(u_i) (last iteration's)
static __device__ float  g_part[(size_t)NBLK * MDIM];   // per-block column partial sums
static __device__ float  g_losspart[NBLK];              // per-block loss partials
static __device__ unsigned g_cnt;                       // grid-barrier arrive counter
static __device__ unsigned g_gen;                       // grid-barrier generation

__device__ __forceinline__ float warp_sum(float v) {
#pragma unroll
    for (int o = 16; o; o >>= 1) v += __shfl_xor_sync(0xffffffffu, v, o);
    return v;
}
__device__ __forceinline__ float warp_max(float v) {
#pragma unroll
    for (int o = 16; o; o >>= 1) v = fmaxf(v, __shfl_xor_sync(0xffffffffu, v, o));
    return v;
}

// Device-wide barrier: all NBLK CTAs resident (one wave, occ 1). Deterministic.
__device__ __forceinline__ void grid_bar(unsigned want) {
    __syncthreads();
    if (threadIdx.x == 0) {
        __threadfence();
        unsigned a = atomicAdd(&g_cnt, 1u);
        if (a == NBLK - 1u) {
            atomicExch(&g_cnt, 0u);
            __threadfence();
            atomicExch(&g_gen, want);           // release
        } else {
            while (*((volatile unsigned*)&g_gen) < want) __nanosleep(64);
        }
        __threadfence();                         // acquire
    }
    __syncthreads();
}

// barrier reset + w <- 1  (runs once per graph replay)
__global__ void k_init() {
    int j = blockIdx.x * blockDim.x + threadIdx.x;
    if (j < MDIM) g_w[j] = 1.0f;
    if (j == 0) { g_cnt = 0u; g_gen = 0u; }
}

// E = exp(s) in fp16 (one pass; iterations read half the bytes and do NO exp)
__global__ void k_convert(const float* __restrict__ in) {
    const float L2E = 1.4426950408889634f;
    size_t i = (size_t)blockIdx.x * blockDim.x + threadIdx.x;   // float4 index
    float4 f = reinterpret_cast<const float4*>(in)[i];
    float e0 = exp2f(f.x * L2E), e1 = exp2f(f.y * L2E);
    float e2 = exp2f(f.z * L2E), e3 = exp2f(f.w * L2E);
    union { uint2 u; __half2 h[2]; } P;
    P.h[0] = __floats2half2_rn(e0, e1);
    P.h[1] = __floats2half2_rn(e2, e3);
    reinterpret_cast<uint2*>(g_E)[i] = P.u;
}

// unpack one uint4 of half2 E-values into 8 floats and fma into lsum with w
__device__ __forceinline__ void unpack_row_seg(uint4 u, const float* __restrict__ w,
                                               float* __restrict__ e, float& lsum) {
    union { uint4 u; __half2 h[4]; } P; P.u = u;
#pragma unroll
    for (int q = 0; q < 4; q++) {
        float2 f = __half22float2(P.h[q]);
        e[2 * q]     = f.x;
        e[2 * q + 1] = f.y;
        lsum = fmaf(f.x, w[2 * q],     lsum);
        lsum = fmaf(f.y, w[2 * q + 1], lsum);
    }
}

// Persistent multiplicative Sinkhorn. Rows processed in PAIRS with a single
// parity-buffered __syncthreads per pair (0.5 syncs/row vs 2/row before).
//   S_i = sum_j E_ij*w_j ; z_i = mu/S_i ; colsum_j = sum_i E_ij*z_i ; w_j = nu/colsum_j
// Thread t owns 16 columns { (g<<12) + 8t .. +7 : g=0..1 }.
__global__ void __launch_bounds__(TPB, 1) k_sinkhorn() {
    const int tid = threadIdx.x;
    const int b   = blockIdx.x;
    const int r0  = (b * MDIM) / NBLK;
    const int r1  = ((b + 1) * MDIM) / NBLK;
    const float MUc = 6.103515625e-5f;        // mu = nu = 1/16384

    // column-reduce ownership (same [c0,c1) as rows); 8 groups of 64 lanes,
    // groups 0-3 sum 19 partial rows, groups 4-7 sum 18 (4*19+4*18 = 148).
    const int c0 = r0, nc = r1 - r0;
    const int cl = tid & 63;
    const int cg = tid >> 6;
    const int cbase = cg * 18 + min(cg, 4);

    __shared__ float sred[2][2][16];   // [parity][row-in-pair][warp]
    __shared__ float csum[8][64];

    float w[16];
#pragma unroll
    for (int k = 0; k < 16; k++) w[k] = 1.0f;     // v = 0 at iteration 1

    // prefetch rows r0, r0+1 (every block has >= 55 rows)
    uint4 raw[2][2];
    {
        const uint4* rA = reinterpret_cast<const uint4*>(g_E + (size_t)r0 * MDIM);
        const uint4* rB = reinterpret_cast<const uint4*>(g_E + (size_t)(r0 + 1) * MDIM);
#pragma unroll
        for (int g = 0; g < 2; g++) { raw[0][g] = rA[(g << 9) + tid]; raw[1][g] = rB[(g << 9) + tid]; }
    }

    unsigned gen = 0;

    for (int it = 0; it < NITER; it++) {
        float cacc[16];
#pragma unroll
        for (int k = 0; k < 16; k++) cacc[k] = 0.f;

        int pp = 0;   // sync-round parity
        int r  = r0;

        // ---- row phase: pairs of rows, ONE __syncthreads per pair ----
        for (; r + 1 < r1; r += 2, pp ^= 1) {
            uint4 a0 = raw[0][0], a1 = raw[0][1];       // row r
            uint4 b0 = raw[1][0], b1 = raw[1][1];       // row r+1
            if (r + 2 < r1) {
                const uint4* rw = reinterpret_cast<const uint4*>(g_E + (size_t)(r + 2) * MDIM);
                raw[0][0] = rw[tid]; raw[0][1] = rw[(1 << 9) + tid];
            }
            if (r + 3 < r1) {
                const uint4* rw = reinterpret_cast<const uint4*>(g_E + (size_t)(r + 3) * MDIM);
                raw[1][0] = rw[tid]; raw[1][1] = rw[(1 << 9) + tid];
            }

            float e0[16], e1[16];
            float l0 = 0.f, l1 = 0.f;
            unpack_row_seg(a0, w,     e0,     l0);
            unpack_row_seg(a1, w + 8, e0 + 8, l0);
            unpack_row_seg(b0, w,     e1,     l1);
            unpack_row_seg(b1, w + 8, e1 + 8, l1);

            float ws0 = warp_sum(l0);
            float ws1 = warp_sum(l1);
            if ((tid & 31) == 0) {
                sred[pp][0][tid >> 5] = ws0;
                sred[pp][1][tid >> 5] = ws1;
            }
            __syncthreads();                            // the ONLY barrier this pair
            float S0 = 0.f, S1 = 0.f;
#pragma unroll
            for (int q = 0; q < 16; q++) { S0 += sred[pp][0][q]; S1 += sred[pp][1][q]; }

            float z0 = __fdividef(MUc, S0);
            float z1 = __fdividef(MUc, S1);
            if (tid == 0) { g_z[r] = z0; g_z[r + 1] = z1; }

#pragma unroll
            for (int k = 0; k < 16; k++) {
                cacc[k] = fmaf(e0[k], z0, cacc[k]);
                cacc[k] = fmaf(e1[k], z1, cacc[k]);
            }
        }
        // tail row (blocks with odd row count)
        if (r < r1) {
            uint4 a0 = raw[0][0], a1 = raw[0][1];
            float e0[16];
            float l0 = 0.f;
            unpack_row_seg(a0, w,     e0,     l0);
            unpack_row_seg(a1, w + 8, e0 + 8, l0);
            float ws0 = warp_sum(l0);
            if ((tid & 31) == 0) sred[pp][0][tid >> 5] = ws0;
            __syncthreads();
            float S0 = 0.f;
#pragma unroll
            for (int q = 0; q < 16; q++) S0 += sred[pp][0][q];
            float z0 = __fdividef(MUc, S0);
            if (tid == 0) g_z[r] = z0;
#pragma unroll
            for (int k = 0; k < 16; k++) cacc[k] = fmaf(e0[k], z0, cacc[k]);
        }

        // writeout column partials
        {
            float* outp = g_part + (size_t)b * MDIM;
#pragma unroll
            for (int g = 0; g < 2; g++) {
                int cb = (g << 12) + (tid << 3);
                float4 o0, o1;
                o0.x = cacc[g * 8 + 0]; o0.y = cacc[g * 8 + 1];
                o0.z = cacc[g * 8 + 2]; o0.w = cacc[g * 8 + 3];
                o1.x = cacc[g * 8 + 4]; o1.y = cacc[g * 8 + 5];
                o1.z = cacc[g * 8 + 6]; o1.w = cacc[g * 8 + 7];
                *reinterpret_cast<float4*>(outp + cb)     = o0;
                *reinterpret_cast<float4*>(outp + cb + 4) = o1;
            }
        }

        grid_bar(++gen);    // partials visible everywhere

        // ---- column reduce: w_j = nu / sum_b P[b][j] for my columns ----
        {
            float s = 0.f;
            if (cl < nc) {
                const float* p = g_part + (size_t)cbase * MDIM + (c0 + cl);
#pragma unroll
                for (int k = 0; k < 18; k++) s += p[(size_t)k * MDIM];
                if (cg < 4) s += p[(size_t)18 * MDIM];
            }
            csum[cg][cl] = s;
            __syncthreads();
            if (cg == 0 && cl < nc) {
                float t = 0.f;
#pragma unroll
                for (int q = 0; q < 8; q++) t += csum[q][cl];    // fixed order
                g_w[c0 + cl] = __fdividef(MUc, t);
            }
        }

        // prefetch next iteration's first two rows (independent of w)
        if (it + 1 < NITER) {
            const uint4* rA = reinterpret_cast<const uint4*>(g_E + (size_t)r0 * MDIM);
            const uint4* rB = reinterpret_cast<const uint4*>(g_E + (size_t)(r0 + 1) * MDIM);
#pragma unroll
            for (int g = 0; g < 2; g++) { raw[0][g] = rA[(g << 9) + tid]; raw[1][g] = rB[(g << 9) + tid]; }
        }

        grid_bar(++gen);    // w visible everywhere

        if (it + 1 < NITER) {
#pragma unroll
            for (int g = 0; g < 2; g++) {
                int cb = (g << 12) + (tid << 3);
                float4 a = *reinterpret_cast<const float4*>(g_w + cb);
                float4 c = *reinterpret_cast<const float4*>(g_w + cb + 4);
                w[g * 8 + 0] = a.x; w[g * 8 + 1] = a.y; w[g * 8 + 2] = a.z; w[g * 8 + 3] = a.w;
                w[g * 8 + 4] = c.x; w[g * 8 + 5] = c.y; w[g * 8 + 6] = c.z; w[g * 8 + 7] = c.w;
            }
        }
    }
}

// Final loss pass over the fp32 matrix. ONE __syncthreads per row:
// per-warp max-shifted partials; warp 0 recombines (1 exp2/lane + shuffles).
//  L_i = LSE_j(scale*s); base = exp(s)*w_j; rowq = z_i*16384
//  per_row = beta*(L*SumQ - scale*Sum(s*Q)) + (1-beta)*(L - scale*s_ii)
__global__ void __launch_bounds__(TPB, 1) k_final(const float* __restrict__ Sm,
                                                  const float* __restrict__ scale_p) {
    const int tid = threadIdx.x;
    const int b   = blockIdx.x;
    const int r0  = (b * MDIM) / NBLK;
    const int r1  = ((b + 1) * MDIM) / NBLK;
    const float L2E   = 1.4426950408889634f;
    const float scale = *scale_p;
    const float sL2E  = scale * L2E;

    float w[16];
#pragma unroll
    for (int g = 0; g < 2; g++) {
        int cb = (g << 12) + (tid << 3);
        float4 a = *reinterpret_cast<const float4*>(g_w + cb);
        float4 c = *reinterpret_cast<const float4*>(g_w + cb + 4);
        w[g * 8 + 0] = a.x; w[g * 8 + 1] = a.y; w[g * 8 + 2] = a.z; w[g * 8 + 3] = a.w;
        w[g * 8 + 4] = c.x; w[g * 8 + 5] = c.y; w[g * 8 + 6] = c.z; w[g * 8 + 7] = c.w;
    }

    __shared__ float sM[2][16], sA[2][16], sB[2][16], sC[2][16];
    __shared__ float sdiag[2];
    float rowloss = 0.f;

    float4 nxt[4];
    {
        const float4* row = reinterpret_cast<const float4*>(Sm + (size_t)r0 * MDIM);
#pragma unroll
        for (int g = 0; g < 2; g++) {
            nxt[2 * g]     = row[(g << 10) + (tid << 1)];
            nxt[2 * g + 1] = row[(g << 10) + (tid << 1) + 1];
        }
    }

    for (int r = r0; r < r1; r++) {
        const int p = (r - r0) & 1;
        float val[16];
#pragma unroll
        for (int g = 0; g < 2; g++) {
            float4 a = nxt[2 * g], c = nxt[2 * g + 1];
            val[g * 8 + 0] = a.x; val[g * 8 + 1] = a.y; val[g * 8 + 2] = a.z; val[g * 8 + 3] = a.w;
            val[g * 8 + 4] = c.x; val[g * 8 + 5] = c.y; val[g * 8 + 6] = c.z; val[g * 8 + 7] = c.w;
        }
        if (r + 1 < r1) {
            const float4* row = reinterpret_cast<const float4*>(Sm + (size_t)(r + 1) * MDIM);
#pragma unroll
            for (int g = 0; g < 2; g++) {
                nxt[2 * g]     = row[(g << 10) + (tid << 1)];
                nxt[2 * g + 1] = row[(g << 10) + (tid << 1) + 1];
            }
        }

        float m = val[0];
#pragma unroll
        for (int k = 1; k < 16; k++) m = fmaxf(m, val[k]);
        float mw = warp_max(m);                       // per-warp max

        float negmwL = -mw * sL2E;
        float aE = 0.f, aB = 0.f, aSB = 0.f;
#pragma unroll
        for (int k = 0; k < 16; k++) {
            float s = val[k];
            aE += exp2f(fmaf(s, sL2E, negmwL));       // exp(scale*(s-mw)) <= 1
            float base = exp2f(s * L2E) * w[k];       // exp(s+v)
            aB += base;
            aSB = fmaf(s, base, aSB);
        }
        aE = warp_sum(aE); aB = warp_sum(aB); aSB = warp_sum(aSB);

        if (tid == ((r & 4095) >> 3)) sdiag[p] = val[((r >> 12) << 3) + (r & 7)]; // col r owner
        if ((tid & 31) == 0) {
            int q = tid >> 5;
            sM[p][q] = mw; sA[p][q] = aE; sB[p][q] = aB; sC[p][q] = aSB;
        }
        __syncthreads();                              // the ONLY barrier this row

        if (tid < 32) {                               // warp 0 recombines
            int q = tid & 15;
            float mq = sM[p][q];
            float M  = warp_max((tid < 16) ? mq : -3.4e38f);
            float tE = (tid < 16) ? exp2f((mq - M) * sL2E) * sA[p][q] : 0.f;
            float tB = (tid < 16) ? sB[p][q] : 0.f;
            float tC = (tid < 16) ? sC[p][q] : 0.f;
            float SE = warp_sum(tE);
            float SB = warp_sum(tB);
            float SC = warp_sum(tC);
            if (tid == 0) {
                float L    = fmaf(scale, M, __logf(SE));
                float rowq = g_z[r] * 16384.0f;       // exp(u + log(m+n))
                rowloss += BETA * (L * (SB * rowq) - scale * (SC * rowq))
                         + (1.f - BETA) * (L - scale * sdiag[p]);
            }
        }
    }
    if (tid == 0) g_losspart[b] = rowloss;
}

// final scalar: mean over rows (fixed-order reduction -> deterministic)
__global__ void k_loss(float* __restrict__ out) {
    int tid = threadIdx.x;
    float v = (tid < NBLK) ? g_losspart[tid] : 0.f;
    v = warp_sum(v);
    __shared__ float sred[8];
    if ((tid & 31) == 0) sred[tid >> 5] = v;
    __syncthreads();
    if (tid == 0) {
        float t = 0.f;
#pragma unroll
        for (int q = 0; q < 8; q++) t += sred[q];
        out[0] = t / (float)MDIM;
    }
}

extern "C" void kernel_launch(void* const* d_in, const int* in_sizes, int n_in,
                              void* d_out, int out_size) {
    (void)in_sizes; (void)n_in; (void)out_size;
    const float* Sm    = (const float*)d_in[0];   // similarity_matrix [8192,8192] f32
    const float* scale = (const float*)d_in[1];   // logit_scale scalar f32
    float* out = (float*)d_out;

    k_init<<<MDIM / TPB, TPB>>>();
    k_convert<<<(int)(((size_t)MDIM * MDIM / 4) / TPB), TPB>>>(Sm);
    k_sinkhorn<<<NBLK, TPB>>>();
    k_final<<<NBLK, TPB>>>(Sm, scale);
    k_loss<<<1, TPB>>>(out);
}

// round 10
// speedup vs baseline: 1.7771x; 1.0369x over previous
#include <cuda_runtime.h>
#include <cuda_fp16.h>
#include <cstdint>

// Problem constants (fixed by the reference: m = n = 8192, 50 Sinkhorn iters, beta=0.3)
#define MDIM  8192
#define NBLK  148          // <= SM count -> one resident wave at occ 1
#define TPB   512
#define NITER 50
#define BETA  0.3f
#define DEPTH 6            // smem ring depth in rows (6 x 16KB = 96KB dynamic smem)
#define ROWU4 1024         // uint4 per row (8192 halves)

// ---- scratch (device globals: no allocation allowed in kernel_launch) ----
static __device__ __half g_E[(size_t)MDIM * MDIM];      // E = exp(s) in fp16 (128 MB)
static __device__ float  g_w[MDIM];                     // w_j = exp(v_j)
static __device__ float  g_z[MDIM];                     // z_i = exp(u_i) (last iteration's)
static __device__ float  g_part[(size_t)NBLK * MDIM];   // per-block column partial sums
static __device__ float  g_losspart[NBLK];              // per-block loss partials
static __device__ unsigned g_cnt;                       // grid-barrier arrive counter
static __device__ unsigned g_gen;                       // grid-barrier generation

__device__ __forceinline__ float warp_sum(float v) {
#pragma unroll
    for (int o = 16; o; o >>= 1) v += __shfl_xor_sync(0xffffffffu, v, o);
    return v;
}
__device__ __forceinline__ float warp_max(float v) {
#pragma unroll
    for (int o = 16; o; o >>= 1) v = fmaxf(v, __shfl_xor_sync(0xffffffffu, v, o));
    return v;
}

// ---- packed f32x2 helpers (sm_103a FFMA2/FADD2 via PTX only) ----
__device__ __forceinline__ unsigned long long pk2(float x, float y) {
    unsigned long long u; asm("mov.b64 %0,{%1,%2};" : "=l"(u) : "f"(x), "f"(y)); return u;
}
__device__ __forceinline__ void upk2(unsigned long long u, float& x, float& y) {
    asm("mov.b64 {%0,%1},%2;" : "=f"(x), "=f"(y) : "l"(u));
}
__device__ __forceinline__ unsigned long long fma2(unsigned long long a, unsigned long long b,
                                                   unsigned long long c) {
    unsigned long long d;
    asm("fma.rn.f32x2 %0,%1,%2,%3;" : "=l"(d) : "l"(a), "l"(b), "l"(c));
    return d;
}
__device__ __forceinline__ unsigned long long add2p(unsigned long long a, unsigned long long b) {
    unsigned long long d;
    asm("add.rn.f32x2 %0,%1,%2;" : "=l"(d) : "l"(a), "l"(b));
    return d;
}

// ---- cp.async helpers ----
__device__ __forceinline__ void cpa16(uint32_t dst, const void* src) {
    asm volatile("cp.async.cg.shared.global [%0], [%1], 16;" :: "r"(dst), "l"(src));
}
#define CP_COMMIT() asm volatile("cp.async.commit_group;")
#define CP_WAIT(n)  asm volatile("cp.async.wait_group %0;" :: "n"(n))

// Device-wide barrier: all NBLK CTAs resident (one wave, occ 1). Deterministic.
__device__ __forceinline__ void grid_bar(unsigned want) {
    __syncthreads();
    if (threadIdx.x == 0) {
        __threadfence();
        unsigned a = atomicAdd(&g_cnt, 1u);
        if (a == NBLK - 1u) {
            atomicExch(&g_cnt, 0u);
            __threadfence();
            atomicExch(&g_gen, want);           // release
        } else {
            while (*((volatile unsigned*)&g_gen) < want) __nanosleep(64);
        }
        __threadfence();                         // acquire
    }
    __syncthreads();
}

// barrier reset + w <- 1  (runs once per graph replay)
__global__ void k_init() {
    int j = blockIdx.x * blockDim.x + threadIdx.x;
    if (j < MDIM) g_w[j] = 1.0f;
    if (j == 0) { g_cnt = 0u; g_gen = 0u; }
}

// E = exp(s) in fp16 (one pass; iterations read half the bytes and do NO exp)
__global__ void k_convert(const float* __restrict__ in) {
    const float L2E = 1.4426950408889634f;
    size_t i = (size_t)blockIdx.x * blockDim.x + threadIdx.x;   // float4 index
    float4 f = reinterpret_cast<const float4*>(in)[i];
    float e0 = exp2f(f.x * L2E), e1 = exp2f(f.y * L2E);
    float e2 = exp2f(f.z * L2E), e3 = exp2f(f.w * L2E);
    union { uint2 u; __half2 h[2]; } P;
    P.h[0] = __floats2half2_rn(e0, e1);
    P.h[1] = __floats2half2_rn(e2, e3);
    reinterpret_cast<uint2*>(g_E)[i] = P.u;
}

// unpack one uint4 (8 half2-pairs' worth = 4 half2) into 4 packed f32x2 and fma into lsum2
__device__ __forceinline__ void seg_unpack(uint4 u, const unsigned long long* __restrict__ w2,
                                           unsigned long long* __restrict__ e2,
                                           unsigned long long& lsum2) {
    union { uint4 u; __half2 h[4]; } P; P.u = u;
#pragma unroll
    for (int q = 0; q < 4; q++) {
        float2 f = __half22float2(P.h[q]);
        e2[q] = pk2(f.x, f.y);
        lsum2 = fma2(e2[q], w2[q], lsum2);
    }
}

// Persistent multiplicative Sinkhorn.
//   S_i = sum_j E_ij*w_j ; z_i = mu/S_i ; colsum_j = sum_i E_ij*z_i ; w_j = nu/colsum_j
// E rows staged through a DEPTH-row cp.async smem ring (per-thread-private slots ->
// no extra block syncs; ring cycles the same rows across all 50 iterations).
// Rows processed in pairs: ONE __syncthreads per pair. All math packed f32x2.
__global__ void __launch_bounds__(TPB, 1) k_sinkhorn() {
    extern __shared__ uint4 sE4[];                 // DEPTH * ROWU4 uint4
    const int tid = threadIdx.x;
    const int b   = blockIdx.x;
    const int r0  = (b * MDIM) / NBLK;
    const int r1  = ((b + 1) * MDIM) / NBLK;
    const int nrows = r1 - r0;
    const float MUc = 6.103515625e-5f;             // mu = nu = 1/16384

    // column-reduce ownership (same [c0,c1) as rows); 8 groups of 64 lanes,
    // groups 0-3 sum 19 partial rows, groups 4-7 sum 18 (4*19+4*18 = 148).
    const int c0 = r0, nc = nrows;
    const int cl = tid & 63;
    const int cg = tid >> 6;
    const int cbase = cg * 18 + min(cg, 4);

    __shared__ unsigned long long sredp[2][16];    // packed (S_row0, S_row1) per warp
    __shared__ float csum[8][64];

    unsigned long long w2[8];
#pragma unroll
    for (int k = 0; k < 8; k++) w2[k] = pk2(1.0f, 1.0f);   // v = 0 at iteration 1

    // ring issue machinery: virtual row index v -> actual row r0 + (v % nrows), slot v % DEPTH
    const int total = NITER * nrows;
    int icnt = 0;                                  // issued rows
    int ccnt = 0;                                  // consumed rows
    const __half* gband = g_E + (size_t)r0 * MDIM;

    auto issue_row = [&](void) {
        if (icnt < total) {
            int rr   = icnt % nrows;
            int slot = icnt % DEPTH;
            const uint4* src = reinterpret_cast<const uint4*>(gband + (size_t)rr * MDIM);
            uint32_t d0 = (uint32_t)__cvta_generic_to_shared(&sE4[slot * ROWU4 + tid]);
            uint32_t d1 = (uint32_t)__cvta_generic_to_shared(&sE4[slot * ROWU4 + 512 + tid]);
            cpa16(d0, src + tid);
            cpa16(d1, src + 512 + tid);
        }
        CP_COMMIT();                               // always commit: stable accounting
        icnt++;
    };

#pragma unroll
    for (int d = 0; d < DEPTH; d++) issue_row();   // prologue: fill the ring

    unsigned gen = 0;

    for (int it = 0; it < NITER; it++) {
        unsigned long long cacc2[8];
#pragma unroll
        for (int k = 0; k < 8; k++) cacc2[k] = 0ull;

        int pp = 0;
        int r  = r0;

        // ---- row phase: pairs of rows, ONE __syncthreads per pair ----
        for (; r + 1 < r1; r += 2, pp ^= 1) {
            CP_WAIT(DEPTH - 2);                    // 2 oldest rows landed
            const int sA = ccnt % DEPTH;
            const int sB = (ccnt + 1) % DEPTH;
            uint4 a0 = sE4[sA * ROWU4 + tid];
            uint4 a1 = sE4[sA * ROWU4 + 512 + tid];
            uint4 b0 = sE4[sB * ROWU4 + tid];
            uint4 b1 = sE4[sB * ROWU4 + 512 + tid];
            ccnt += 2;
            issue_row();                           // refill both slots
            issue_row();

            unsigned long long eA[8], eB[8];
            unsigned long long l0 = 0ull, l1 = 0ull;
            seg_unpack(a0, w2,     eA,     l0);
            seg_unpack(a1, w2 + 4, eA + 4, l0);
            seg_unpack(b0, w2,     eB,     l1);
            seg_unpack(b1, w2 + 4, eB + 4, l1);

            float x0, y0, x1, y1;
            upk2(l0, x0, y0); upk2(l1, x1, y1);
            float ws0 = warp_sum(x0 + y0);
            float ws1 = warp_sum(x1 + y1);
            if ((tid & 31) == 0) sredp[pp][tid >> 5] = pk2(ws0, ws1);
            __syncthreads();                       // the ONLY barrier this pair

            unsigned long long S2 = sredp[pp][0];
#pragma unroll
            for (int q = 1; q < 16; q++) S2 = add2p(S2, sredp[pp][q]);  // fixed order
            float S0, S1; upk2(S2, S0, S1);

            float z0 = __fdividef(MUc, S0);
            float z1 = __fdividef(MUc, S1);
            if (tid == 0) { g_z[r] = z0; g_z[r + 1] = z1; }

            unsigned long long z00 = pk2(z0, z0), z11 = pk2(z1, z1);
#pragma unroll
            for (int k = 0; k < 8; k++) {
                cacc2[k] = fma2(eA[k], z00, cacc2[k]);
                cacc2[k] = fma2(eB[k], z11, cacc2[k]);
            }
        }
        // tail row (blocks with odd row count)
        if (r < r1) {
            CP_WAIT(DEPTH - 1);
            const int sA = ccnt % DEPTH;
            uint4 a0 = sE4[sA * ROWU4 + tid];
            uint4 a1 = sE4[sA * ROWU4 + 512 + tid];
            ccnt += 1;
            issue_row();

            unsigned long long eA[8];
            unsigned long long l0 = 0ull;
            seg_unpack(a0, w2,     eA,     l0);
            seg_unpack(a1, w2 + 4, eA + 4, l0);
            float x0, y0; upk2(l0, x0, y0);
            float ws0 = warp_sum(x0 + y0);
            if ((tid & 31) == 0) sredp[pp][tid >> 5] = pk2(ws0, 0.f);
            __syncthreads();
            unsigned long long S2 = sredp[pp][0];
#pragma unroll
            for (int q = 1; q < 16; q++) S2 = add2p(S2, sredp[pp][q]);
            float S0, S1; upk2(S2, S0, S1);
            float z0 = __fdividef(MUc, S0);
            if (tid == 0) g_z[r] = z0;
            unsigned long long z00 = pk2(z0, z0);
#pragma unroll
            for (int k = 0; k < 8; k++) cacc2[k] = fma2(eA[k], z00, cacc2[k]);
        }

        // writeout column partials
        {
            float* outp = g_part + (size_t)b * MDIM;
#pragma unroll
            for (int g = 0; g < 2; g++) {
                int cb = (g << 12) + (tid << 3);
                float4 o0, o1;
                upk2(cacc2[g * 4 + 0], o0.x, o0.y);
                upk2(cacc2[g * 4 + 1], o0.z, o0.w);
                upk2(cacc2[g * 4 + 2], o1.x, o1.y);
                upk2(cacc2[g * 4 + 3], o1.z, o1.w);
                *reinterpret_cast<float4*>(outp + cb)     = o0;
                *reinterpret_cast<float4*>(outp + cb + 4) = o1;
            }
        }

        grid_bar(++gen);    // partials visible everywhere

        // ---- column reduce: w_j = nu / sum_b P[b][j] for my columns ----
        {
            float s = 0.f;
            if (cl < nc) {
                const float* p = g_part + (size_t)cbase * MDIM + (c0 + cl);
#pragma unroll
                for (int k = 0; k < 18; k++) s += p[(size_t)k * MDIM];
                if (cg < 4) s += p[(size_t)18 * MDIM];
            }
            csum[cg][cl] = s;
            __syncthreads();
            if (cg == 0 && cl < nc) {
                float t = 0.f;
#pragma unroll
                for (int q = 0; q < 8; q++) t += csum[q][cl];    // fixed order
                g_w[c0 + cl] = __fdividef(MUc, t);
            }
        }

        grid_bar(++gen);    // w visible everywhere

        if (it + 1 < NITER) {
#pragma unroll
            for (int g = 0; g < 2; g++) {
                int cb = (g << 12) + (tid << 3);
                float4 a = *reinterpret_cast<const float4*>(g_w + cb);
                float4 c = *reinterpret_cast<const float4*>(g_w + cb + 4);
                w2[g * 4 + 0] = pk2(a.x, a.y);
                w2[g * 4 + 1] = pk2(a.z, a.w);
                w2[g * 4 + 2] = pk2(c.x, c.y);
                w2[g * 4 + 3] = pk2(c.z, c.w);
            }
        }
    }
}

// Final loss pass over the fp32 matrix. ONE __syncthreads per row:
// per-warp max-shifted partials; warp 0 recombines (1 exp2/lane + shuffles).
//  L_i = LSE_j(scale*s); base = exp(s)*w_j; rowq = z_i*16384
//  per_row = beta*(L*SumQ - scale*Sum(s*Q)) + (1-beta)*(L - scale*s_ii)
__global__ void __launch_bounds__(TPB, 1) k_final(const float* __restrict__ Sm,
                                                  const float* __restrict__ scale_p) {
    const int tid = threadIdx.x;
    const int b   = blockIdx.x;
    const int r0  = (b * MDIM) / NBLK;
    const int r1  = ((b + 1) * MDIM) / NBLK;
    const float L2E   = 1.4426950408889634f;
    const float scale = *scale_p;
    const float sL2E  = scale * L2E;

    float w[16];
#pragma unroll
    for (int g = 0; g < 2; g++) {
        int cb = (g << 12) + (tid << 3);
        float4 a = *reinterpret_cast<const float4*>(g_w + cb);
        float4 c = *reinterpret_cast<const float4*>(g_w + cb + 4);
        w[g * 8 + 0] = a.x; w[g * 8 + 1] = a.y; w[g * 8 + 2] = a.z; w[g * 8 + 3] = a.w;
        w[g * 8 + 4] = c.x; w[g * 8 + 5] = c.y; w[g * 8 + 6] = c.z; w[g * 8 + 7] = c.w;
    }

    __shared__ float sM[2][16], sA[2][16], sB[2][16], sC[2][16];
    __shared__ float sdiag[2];
    float rowloss = 0.f;

    float4 nxt[4];
    {
        const float4* row = reinterpret_cast<const float4*>(Sm + (size_t)r0 * MDIM);
#pragma unroll
        for (int g = 0; g < 2; g++) {
            nxt[2 * g]     = row[(g << 10) + (tid << 1)];
            nxt[2 * g + 1] = row[(g << 10) + (tid << 1) + 1];
        }
    }

    for (int r = r0; r < r1; r++) {
        const int p = (r - r0) & 1;
        float val[16];
#pragma unroll
        for (int g = 0; g < 2; g++) {
            float4 a = nxt[2 * g], c = nxt[2 * g + 1];
            val[g * 8 + 0] = a.x; val[g * 8 + 1] = a.y; val[g * 8 + 2] = a.z; val[g * 8 + 3] = a.w;
            val[g * 8 + 4] = c.x; val[g * 8 + 5] = c.y; val[g * 8 + 6] = c.z; val[g * 8 + 7] = c.w;
        }
        if (r + 1 < r1) {
            const float4* row = reinterpret_cast<const float4*>(Sm + (size_t)(r + 1) * MDIM);
#pragma unroll
            for (int g = 0; g < 2; g++) {
                nxt[2 * g]     = row[(g << 10) + (tid << 1)];
                nxt[2 * g + 1] = row[(g << 10) + (tid << 1) + 1];
            }
        }

        float m = val[0];
#pragma unroll
        for (int k = 1; k < 16; k++) m = fmaxf(m, val[k]);
        float mw = warp_max(m);                       // per-warp max

        float negmwL = -mw * sL2E;
        float aE = 0.f, aB = 0.f, aSB = 0.f;
#pragma unroll
        for (int k = 0; k < 16; k++) {
            float s = val[k];
            aE += exp2f(fmaf(s, sL2E, negmwL));       // exp(scale*(s-mw)) <= 1
            float base = exp2f(s * L2E) * w[k];       // exp(s+v)
            aB += base;
            aSB = fmaf(s, base, aSB);
        }
        aE = warp_sum(aE); aB = warp_sum(aB); aSB = warp_sum(aSB);

        if (tid == ((r & 4095) >> 3)) sdiag[p] = val[((r >> 12) << 3) + (r & 7)]; // col r owner
        if ((tid & 31) == 0) {
            int q = tid >> 5;
            sM[p][q] = mw; sA[p][q] = aE; sB[p][q] = aB; sC[p][q] = aSB;
        }
        __syncthreads();                              // the ONLY barrier this row

        if (tid < 32) {                               // warp 0 recombines
            int q = tid & 15;
            float mq = sM[p][q];
            float M  = warp_max((tid < 16) ? mq : -3.4e38f);
            float tE = (tid < 16) ? exp2f((mq - M) * sL2E) * sA[p][q] : 0.f;
            float tB = (tid < 16) ? sB[p][q] : 0.f;
            float tC = (tid < 16) ? sC[p][q] : 0.f;
            float SE = warp_sum(tE);
            float SB = warp_sum(tB);
            float SC = warp_sum(tC);
            if (tid == 0) {
                float L    = fmaf(scale, M, __logf(SE));
                float rowq = g_z[r] * 16384.0f;       // exp(u + log(m+n))
                rowloss += BETA * (L * (SB * rowq) - scale * (SC * rowq))
                         + (1.f - BETA) * (L - scale * sdiag[p]);
            }
        }
    }
    if (tid == 0) g_losspart[b] = rowloss;
}

// final scalar: mean over rows (fixed-order reduction -> deterministic)
__global__ void k_loss(float* __restrict__ out) {
    int tid = threadIdx.x;
    float v = (tid < NBLK) ? g_losspart[tid] : 0.f;
    v = warp_sum(v);
    __shared__ float sred[8];
    if ((tid & 31) == 0) sred[tid >> 5] = v;
    __syncthreads();
    if (tid == 0) {
        float t = 0.f;
#pragma unroll
        for (int q = 0; q < 8; q++) t += sred[q];
        out[0] = t / (float)MDIM;
    }
}

extern "C" void kernel_launch(void* const* d_in, const int* in_sizes, int n_in,
                              void* d_out, int out_size) {
    (void)in_sizes; (void)n_in; (void)out_size;
    const float* Sm    = (const float*)d_in[0];   // similarity_matrix [8192,8192] f32
    const float* scale = (const float*)d_in[1];   // logit_scale scalar f32
    float* out = (float*)d_out;

    const int dynsmem = DEPTH * ROWU4 * 16;       // 96 KB smem ring
    static int attr_set = 0;
    if (!attr_set) {                              // idempotent, host-side, not captured
        cudaFuncSetAttribute(k_sinkhorn, cudaFuncAttributeMaxDynamicSharedMemorySize, dynsmem);
        attr_set = 1;
    }

    k_init<<<MDIM / TPB, TPB>>>();
    k_convert<<<(int)(((size_t)MDIM * MDIM / 4) / TPB), TPB>>>(Sm);
    k_sinkhorn<<<NBLK, TPB, dynsmem>>>();
    k_final<<<NBLK, TPB>>>(Sm, scale);
    k_loss<<<1, TPB>>>(out);
}

// round 11
// speedup vs baseline: 1.9882x; 1.1188x over previous
#include <cuda_runtime.h>
#include <cuda_fp16.h>
#include <cuda_fp8.h>
#include <cstdint>

// Problem constants (fixed by the reference: m = n = 8192, 50 Sinkhorn iters, beta=0.3)
#define MDIM  8192
#define NBLK  148          // <= SM count -> one resident wave at occ 1
#define TPB   512
#define NITER 50
#define BETA  0.3f
#define DEPTH 12           // smem ring depth in rows (12 x 8KB = 96KB dynamic smem)
#define ROWU4 512          // uint4 per fp8 row (8192 bytes)

// z is carried SCALED: z' = z * 2^20 (true z ~5e-9 underflows fp16).
// The scale cancels in the w update: z' = 64/S, w = 64/colsum' (2^-14 * 2^20 = 2^6).
#define ZSCALE_K 64.0f
#define RQ_FIX   0.015625f // rowq = z*16384 = z' * 16384/2^20 = z'/64

// ---- scratch (device globals: no allocation allowed in kernel_launch) ----
static __device__ uint32_t g_E8[(size_t)MDIM * MDIM / 4]; // E = exp(s) in e4m3 (64 MB)
static __device__ float  g_w[MDIM];                     // w_j = exp(v_j)
static __device__ float  g_z[MDIM];                     // z'_i = exp(u_i)*2^20 (last iter's)
static __device__ float  g_part[(size_t)NBLK * MDIM];   // per-block column partial sums
static __device__ float  g_losspart[NBLK];              // per-block loss partials
static __device__ unsigned g_cnt;                       // grid-barrier arrive counter
static __device__ unsigned g_gen;                       // grid-barrier generation

__device__ __forceinline__ float warp_sum(float v) {
#pragma unroll
    for (int o = 16; o; o >>= 1) v += __shfl_xor_sync(0xffffffffu, v, o);
    return v;
}
__device__ __forceinline__ float warp_max(float v) {
#pragma unroll
    for (int o = 16; o; o >>= 1) v = fmaxf(v, __shfl_xor_sync(0xffffffffu, v, o));
    return v;
}

// ---- packed f32x2 helpers (sm_103a FADD2 via PTX) ----
__device__ __forceinline__ unsigned long long pk2(float x, float y) {
    unsigned long long u; asm("mov.b64 %0,{%1,%2};" : "=l"(u) : "f"(x), "f"(y)); return u;
}
__device__ __forceinline__ void upk2(unsigned long long u, float& x, float& y) {
    asm("mov.b64 {%0,%1},%2;" : "=f"(x), "=f"(y) : "l"(u));
}
__device__ __forceinline__ unsigned long long add2p(unsigned long long a, unsigned long long b) {
    unsigned long long d;
    asm("add.rn.f32x2 %0,%1,%2;" : "=l"(d) : "l"(a), "l"(b));
    return d;
}

// ---- fp8 -> half2 ----
__device__ __forceinline__ __half2 cvt8(unsigned short p) {
    __half2_raw r = __nv_cvt_fp8x2_to_halfraw2((__nv_fp8x2_storage_t)p, __NV_E4M3);
    return *reinterpret_cast<__half2*>(&r);
}

// ---- cp.async helpers ----
__device__ __forceinline__ void cpa16(uint32_t dst, const void* src) {
    asm volatile("cp.async.cg.shared.global [%0], [%1], 16;" :: "r"(dst), "l"(src));
}
#define CP_COMMIT() asm volatile("cp.async.commit_group;")
#define CP_WAIT(n)  asm volatile("cp.async.wait_group %0;" :: "n"(n))

// Device-wide barrier: all NBLK CTAs resident (one wave, occ 1). Deterministic.
__device__ __forceinline__ void grid_bar(unsigned want) {
    __syncthreads();
    if (threadIdx.x == 0) {
        __threadfence();
        unsigned a = atomicAdd(&g_cnt, 1u);
        if (a == NBLK - 1u) {
            atomicExch(&g_cnt, 0u);
            __threadfence();
            atomicExch(&g_gen, want);           // release
        } else {
            while (*((volatile unsigned*)&g_gen) < want) __nanosleep(64);
        }
        __threadfence();                         // acquire
    }
    __syncthreads();
}

// barrier reset + w <- 1  (runs once per graph replay)
__global__ void k_init() {
    int j = blockIdx.x * blockDim.x + threadIdx.x;
    if (j < MDIM) g_w[j] = 1.0f;
    if (j == 0) { g_cnt = 0u; g_gen = 0u; }
}

// E = exp(s) in e4m3 (one pass; iterations read 1/4 of the fp32 bytes, do NO exp)
// low byte of each fp8x2 = even column (matches __nv_cvt_float2_to_fp8x2: x -> low).
__global__ void k_convert(const float* __restrict__ in) {
    const float L2E = 1.4426950408889634f;
    size_t i = (size_t)blockIdx.x * blockDim.x + threadIdx.x;   // float4 index
    float4 f = reinterpret_cast<const float4*>(in)[i];
    float e0 = exp2f(f.x * L2E), e1 = exp2f(f.y * L2E);
    float e2 = exp2f(f.z * L2E), e3 = exp2f(f.w * L2E);
    uint32_t lo = __nv_cvt_float2_to_fp8x2(make_float2(e0, e1), __NV_SATFINITE, __NV_E4M3);
    uint32_t hi = __nv_cvt_float2_to_fp8x2(make_float2(e2, e3), __NV_SATFINITE, __NV_E4M3);
    g_E8[i] = lo | (hi << 16);
}

// unpack one uint4 (16 e4m3) into 8 half2 and hfma2 into lsum with w (half2)
__device__ __forceinline__ void seg_unpack8(uint4 u, const __half2* __restrict__ w2,
                                            __half2* __restrict__ e2, __half2& lsum) {
    uint32_t uu[4] = {u.x, u.y, u.z, u.w};
#pragma unroll
    for (int q = 0; q < 4; q++) {
        __half2 elo = cvt8((unsigned short)(uu[q] & 0xffffu));
        __half2 ehi = cvt8((unsigned short)(uu[q] >> 16));
        e2[2 * q]     = elo;
        e2[2 * q + 1] = ehi;
        lsum = __hfma2(elo, w2[2 * q],     lsum);
        lsum = __hfma2(ehi, w2[2 * q + 1], lsum);
    }
}

// Persistent multiplicative Sinkhorn, fp8 storage + fp16 inner math.
//   S_i = sum_j E_ij*w_j ; z'_i = 64/S_i ; colsum'_j = sum_i E_ij*z'_i ; w_j = 64/colsum'_j
// E rows staged through a DEPTH-row cp.async smem ring (per-thread-private slots).
// Rows processed in pairs: ONE __syncthreads per pair. Thread t owns cols [16t,16t+16).
__global__ void __launch_bounds__(TPB, 1) k_sinkhorn() {
    extern __shared__ uint4 sE4[];                 // DEPTH * ROWU4 uint4
    const int tid = threadIdx.x;
    const int b   = blockIdx.x;
    const int r0  = (b * MDIM) / NBLK;
    const int r1  = ((b + 1) * MDIM) / NBLK;
    const int nrows = r1 - r0;

    // column-reduce ownership (same [c0,c1) as rows); 8 groups of 64 lanes,
    // groups 0-3 sum 19 partial rows, groups 4-7 sum 18 (4*19+4*18 = 148).
    const int c0 = r0, nc = nrows;
    const int cl = tid & 63;
    const int cg = tid >> 6;
    const int cbase = cg * 18 + min(cg, 4);

    __shared__ unsigned long long sredp[2][16];    // packed (S_row0, S_row1) per warp
    __shared__ float csum[8][64];

    __half2 w2[8];
#pragma unroll
    for (int k = 0; k < 8; k++) w2[k] = __float2half2_rn(1.0f);   // v = 0 at iteration 1

    // ring issue machinery: issued row v -> band row v % nrows, slot v % DEPTH
    const int total = NITER * nrows;
    int icnt = 0;
    int ccnt = 0;
    const uint32_t* gband = g_E8 + (size_t)r0 * (MDIM / 4);

    auto issue_row = [&](void) {
        if (icnt < total) {
            int rr   = icnt % nrows;
            int slot = icnt % DEPTH;
            const uint4* src = reinterpret_cast<const uint4*>(gband + (size_t)rr * (MDIM / 4));
            uint32_t d0 = (uint32_t)__cvta_generic_to_shared(&sE4[slot * ROWU4 + tid]);
            cpa16(d0, src + tid);
        }
        CP_COMMIT();                               // always commit: stable accounting
        icnt++;
    };

#pragma unroll
    for (int d = 0; d < DEPTH; d++) issue_row();   // prologue: fill the ring

    unsigned gen = 0;

    for (int it = 0; it < NITER; it++) {
        __half2 cacc[8];
#pragma unroll
        for (int k = 0; k < 8; k++) cacc[k] = __float2half2_rn(0.f);

        int pp = 0;
        int r  = r0;

        // ---- row phase: pairs of rows, ONE __syncthreads per pair ----
        for (; r + 1 < r1; r += 2, pp ^= 1) {
            CP_WAIT(DEPTH - 2);                    // 2 oldest rows landed
            const int sA = ccnt % DEPTH;
            const int sB = (ccnt + 1) % DEPTH;
            uint4 a0 = sE4[sA * ROWU4 + tid];
            uint4 b0 = sE4[sB * ROWU4 + tid];
            ccnt += 2;
            issue_row();                           // refill both slots
            issue_row();

            __half2 eA[8], eB[8];
            __half2 l0 = __float2half2_rn(0.f), l1 = __float2half2_rn(0.f);
            seg_unpack8(a0, w2, eA, l0);
            seg_unpack8(b0, w2, eB, l1);

            float2 f0 = __half22float2(l0);
            float2 f1 = __half22float2(l1);
            float ws0 = warp_sum(f0.x + f0.y);
            float ws1 = warp_sum(f1.x + f1.y);
            if ((tid & 31) == 0) sredp[pp][tid >> 5] = pk2(ws0, ws1);
            __syncthreads();                       // the ONLY barrier this pair

            // 4-deep tree over the 16 warp partials (fixed order -> deterministic)
            unsigned long long t0 = add2p(sredp[pp][0],  sredp[pp][1]);
            unsigned long long t1 = add2p(sredp[pp][2],  sredp[pp][3]);
            unsigned long long t2 = add2p(sredp[pp][4],  sredp[pp][5]);
            unsigned long long t3 = add2p(sredp[pp][6],  sredp[pp][7]);
            unsigned long long t4 = add2p(sredp[pp][8],  sredp[pp][9]);
            unsigned long long t5 = add2p(sredp[pp][10], sredp[pp][11]);
            unsigned long long t6 = add2p(sredp[pp][12], sredp[pp][13]);
            unsigned long long t7 = add2p(sredp[pp][14], sredp[pp][15]);
            t0 = add2p(t0, t1); t2 = add2p(t2, t3); t4 = add2p(t4, t5); t6 = add2p(t6, t7);
            t0 = add2p(t0, t2); t4 = add2p(t4, t6);
            unsigned long long S2 = add2p(t0, t4);
            float S0, S1; upk2(S2, S0, S1);

            float z0 = __fdividef(ZSCALE_K, S0);   // z' = z * 2^20
            float z1 = __fdividef(ZSCALE_K, S1);
            if (tid == 0) { g_z[r] = z0; g_z[r + 1] = z1; }

            __half2 z0h = __float2half2_rn(z0);
            __half2 z1h = __float2half2_rn(z1);
#pragma unroll
            for (int k = 0; k < 8; k++) {
                cacc[k] = __hfma2(eA[k], z0h, cacc[k]);
                cacc[k] = __hfma2(eB[k], z1h, cacc[k]);
            }
        }
        // tail row (blocks with odd row count)
        if (r < r1) {
            CP_WAIT(DEPTH - 1);
            const int sA = ccnt % DEPTH;
            uint4 a0 = sE4[sA * ROWU4 + tid];
            ccnt += 1;
            issue_row();

            __half2 eA[8];
            __half2 l0 = __float2half2_rn(0.f);
            seg_unpack8(a0, w2, eA, l0);
            float2 f0 = __half22float2(l0);
            float ws0 = warp_sum(f0.x + f0.y);
            if ((tid & 31) == 0) sredp[pp][tid >> 5] = pk2(ws0, 0.f);
            __syncthreads();
            unsigned long long S2 = sredp[pp][0];
#pragma unroll
            for (int q = 1; q < 16; q++) S2 = add2p(S2, sredp[pp][q]);
            float S0, S1; upk2(S2, S0, S1);
            float z0 = __fdividef(ZSCALE_K, S0);
            if (tid == 0) g_z[r] = z0;
            __half2 z0h = __float2half2_rn(z0);
#pragma unroll
            for (int k = 0; k < 8; k++) cacc[k] = __hfma2(eA[k], z0h, cacc[k]);
        }

        // writeout column partials (convert fp16 accumulators to fp32 once)
        {
            float* outp = g_part + (size_t)b * MDIM + (tid << 4);
#pragma unroll
            for (int g = 0; g < 4; g++) {
                float2 fa = __half22float2(cacc[2 * g]);
                float2 fb = __half22float2(cacc[2 * g + 1]);
                float4 o; o.x = fa.x; o.y = fa.y; o.z = fb.x; o.w = fb.y;
                *reinterpret_cast<float4*>(outp + 4 * g) = o;
            }
        }

        grid_bar(++gen);    // partials visible everywhere

        // ---- column reduce: w_j = 64 / sum_b P[b][j] for my columns ----
        {
            float s = 0.f;
            if (cl < nc) {
                const float* p = g_part + (size_t)cbase * MDIM + (c0 + cl);
#pragma unroll
                for (int k = 0; k < 18; k++) s += p[(size_t)k * MDIM];
                if (cg < 4) s += p[(size_t)18 * MDIM];
            }
            csum[cg][cl] = s;
            __syncthreads();
            if (cg == 0 && cl < nc) {
                float t = 0.f;
#pragma unroll
                for (int q = 0; q < 8; q++) t += csum[q][cl];    // fixed order
                g_w[c0 + cl] = __fdividef(ZSCALE_K, t);
            }
        }

        grid_bar(++gen);    // w visible everywhere

        if (it + 1 < NITER) {                      // reload my 16 w values (L2-hot)
            const float* wp = g_w + (tid << 4);
            float4 a = *reinterpret_cast<const float4*>(wp);
            float4 c = *reinterpret_cast<const float4*>(wp + 4);
            float4 d = *reinterpret_cast<const float4*>(wp + 8);
            float4 e = *reinterpret_cast<const float4*>(wp + 12);
            w2[0] = __floats2half2_rn(a.x, a.y); w2[1] = __floats2half2_rn(a.z, a.w);
            w2[2] = __floats2half2_rn(c.x, c.y); w2[3] = __floats2half2_rn(c.z, c.w);
            w2[4] = __floats2half2_rn(d.x, d.y); w2[5] = __floats2half2_rn(d.z, d.w);
            w2[6] = __floats2half2_rn(e.x, e.y); w2[7] = __floats2half2_rn(e.z, e.w);
        }
    }
}

// Final loss pass over the fp32 matrix. ONE __syncthreads per row:
// per-warp max-shifted partials; warp 0 recombines (1 exp2/lane + shuffles).
//  L_i = LSE_j(scale*s); base = exp(s)*w_j; rowq = z'_i / 64
//  per_row = beta*(L*SumQ - scale*Sum(s*Q)) + (1-beta)*(L - scale*s_ii)
__global__ void __launch_bounds__(TPB, 1) k_final(const float* __restrict__ Sm,
                                                  const float* __restrict__ scale_p) {
    const int tid = threadIdx.x;
    const int b   = blockIdx.x;
    const int r0  = (b * MDIM) / NBLK;
    const int r1  = ((b + 1) * MDIM) / NBLK;
    const float L2E   = 1.4426950408889634f;
    const float scale = *scale_p;
    const float sL2E  = scale * L2E;

    float w[16];
#pragma unroll
    for (int g = 0; g < 2; g++) {
        int cb = (g << 12) + (tid << 3);
        float4 a = *reinterpret_cast<const float4*>(g_w + cb);
        float4 c = *reinterpret_cast<const float4*>(g_w + cb + 4);
        w[g * 8 + 0] = a.x; w[g * 8 + 1] = a.y; w[g * 8 + 2] = a.z; w[g * 8 + 3] = a.w;
        w[g * 8 + 4] = c.x; w[g * 8 + 5] = c.y; w[g * 8 + 6] = c.z; w[g * 8 + 7] = c.w;
    }

    __shared__ float sM[2][16], sA[2][16], sB[2][16], sC[2][16];
    __shared__ float sdiag[2];
    float rowloss = 0.f;

    float4 nxt[4];
    {
        const float4* row = reinterpret_cast<const float4*>(Sm + (size_t)r0 * MDIM);
#pragma unroll
        for (int g = 0; g < 2; g++) {
            nxt[2 * g]     = row[(g << 10) + (tid << 1)];
            nxt[2 * g + 1] = row[(g << 10) + (tid << 1) + 1];
        }
    }

    for (int r = r0; r < r1; r++) {
        const int p = (r - r0) & 1;
        float val[16];
#pragma unroll
        for (int g = 0; g < 2; g++) {
            float4 a = nxt[2 * g], c = nxt[2 * g + 1];
            val[g * 8 + 0] = a.x; val[g * 8 + 1] = a.y; val[g * 8 + 2] = a.z; val[g * 8 + 3] = a.w;
            val[g * 8 + 4] = c.x; val[g * 8 + 5] = c.y; val[g * 8 + 6] = c.z; val[g * 8 + 7] = c.w;
        }
        if (r + 1 < r1) {
            const float4* row = reinterpret_cast<const float4*>(Sm + (size_t)(r + 1) * MDIM);
#pragma unroll
            for (int g = 0; g < 2; g++) {
                nxt[2 * g]     = row[(g << 10) + (tid << 1)];
                nxt[2 * g + 1] = row[(g << 10) + (tid << 1) + 1];
            }
        }

        float m = val[0];
#pragma unroll
        for (int k = 1; k < 16; k++) m = fmaxf(m, val[k]);
        float mw = warp_max(m);                       // per-warp max

        float negmwL = -mw * sL2E;
        float aE = 0.f, aB = 0.f, aSB = 0.f;
#pragma unroll
        for (int k = 0; k < 16; k++) {
            float s = val[k];
            aE += exp2f(fmaf(s, sL2E, negmwL));       // exp(scale*(s-mw)) <= 1
            float base = exp2f(s * L2E) * w[k];       // exp(s+v)
            aB += base;
            aSB = fmaf(s, base, aSB);
        }
        aE = warp_sum(aE); aB = warp_sum(aB); aSB = warp_sum(aSB);

        if (tid == ((r & 4095) >> 3)) sdiag[p] = val[((r >> 12) << 3) + (r & 7)]; // col r owner
        if ((tid & 31) == 0) {
            int q = tid >> 5;
            sM[p][q] = mw; sA[p][q] = aE; sB[p][q] = aB; sC[p][q] = aSB;
        }
        __syncthreads();                              // the ONLY barrier this row

        if (tid < 32) {                               // warp 0 recombines
            int q = tid & 15;
            float mq = sM[p][q];
            float M  = warp_max((tid < 16) ? mq : -3.4e38f);
            float tE = (tid < 16) ? exp2f((mq - M) * sL2E) * sA[p][q] : 0.f;
            float tB = (tid < 16) ? sB[p][q] : 0.f;
            float tC = (tid < 16) ? sC[p][q] : 0.f;
            float SE = warp_sum(tE);
            float SB = warp_sum(tB);
            float SC = warp_sum(tC);
            if (tid == 0) {
                float L    = fmaf(scale, M, __logf(SE));
                float rowq = g_z[r] * RQ_FIX;         // exp(u + log(m+n))
                rowloss += BETA * (L * (SB * rowq) - scale * (SC * rowq))
                         + (1.f - BETA) * (L - scale * sdiag[p]);
            }
        }
    }
    if (tid == 0) g_losspart[b] = rowloss;
}

// final scalar: mean over rows (fixed-order reduction -> deterministic)
__global__ void k_loss(float* __restrict__ out) {
    int tid = threadIdx.x;
    float v = (tid < NBLK) ? g_losspart[tid] : 0.f;
    v = warp_sum(v);
    __shared__ float sred[8];
    if ((tid & 31) == 0) sred[tid >> 5] = v;
    __syncthreads();
    if (tid == 0) {
        float t = 0.f;
#pragma unroll
        for (int q = 0; q < 8; q++) t += sred[q];
        out[0] = t / (float)MDIM;
    }
}

extern "C" void kernel_launch(void* const* d_in, const int* in_sizes, int n_in,
                              void* d_out, int out_size) {
    (void)in_sizes; (void)n_in; (void)out_size;
    const float* Sm    = (const float*)d_in[0];   // similarity_matrix [8192,8192] f32
    const float* scale = (const float*)d_in[1];   // logit_scale scalar f32
    float* out = (float*)d_out;

    const int dynsmem = DEPTH * ROWU4 * 16;       // 96 KB smem ring
    static int attr_set = 0;
    if (!attr_set) {                              // idempotent, host-side, not captured
        cudaFuncSetAttribute(k_sinkhorn, cudaFuncAttributeMaxDynamicSharedMemorySize, dynsmem);
        attr_set = 1;
    }

    k_init<<<MDIM / TPB, TPB>>>();
    k_convert<<<(int)(((size_t)MDIM * MDIM / 4) / TPB), TPB>>>(Sm);
    k_sinkhorn<<<NBLK, TPB, dynsmem>>>();
    k_final<<<NBLK, TPB>>>(Sm, scale);
    k_loss<<<1, TPB>>>(out);
}